// round 4
// baseline (speedup 1.0000x reference)
#include <cuda_runtime.h>
#include <math.h>

#define D 32
#define H 128
#define B 128
#define NSTEPS 8
#define NTHREADS 512
#define LOG2PI 1.8378770664093453f
#define DT 0.125f

// A[q][p] = W2[p][q] * M[q][p],  M = W1 @ W3  (trace(J) = d2^T (A d1))
__device__ float g_A[H * H];

__global__ void prep_A_kernel(const float* __restrict__ W1,
                              const float* __restrict__ W2,
                              const float* __restrict__ W3) {
    int q = blockIdx.x;
    int p = threadIdx.x;
    float m = 0.f;
#pragma unroll
    for (int i = 0; i < D; ++i)
        m = fmaf(W1[q * D + i], W3[i * H + p], m);
    g_A[q * H + p] = W2[p * H + q] * m;
}

__constant__ float c_c[6] = {0.f, 0.2f, 0.3f, 0.8f, 8.f / 9.f, 1.f};
__constant__ float c_a[6][5] = {
    {0.f, 0.f, 0.f, 0.f, 0.f},
    {0.2f, 0.f, 0.f, 0.f, 0.f},
    {3.f / 40.f, 9.f / 40.f, 0.f, 0.f, 0.f},
    {44.f / 45.f, -56.f / 15.f, 32.f / 9.f, 0.f, 0.f},
    {19372.f / 6561.f, -25360.f / 2187.f, 64448.f / 6561.f, -212.f / 729.f, 0.f},
    {9017.f / 3168.f, -355.f / 33.f, 46732.f / 5247.f, 49.f / 176.f, -5103.f / 18656.f}};
__constant__ float c_b[6] = {35.f / 384.f, 0.f, 500.f / 1113.f, 125.f / 192.f,
                             -2187.f / 6784.f, 11.f / 84.f};

__device__ __forceinline__ float tanh_fast(float x) {
    float r;
    asm("tanh.approx.f32 %0, %1;" : "=f"(r) : "f"(x));
    return r;
}

// shared memory layout (floats)
#define OFF_Z1PART 0
#define OFF_PART2  (OFF_Z1PART + 512)
#define OFF_PART   (OFF_PART2 + 1024)
#define OFF_HD2    (OFF_PART + 512)
#define OFF_TRS    (OFF_HD2 + 256)
#define OFF_H2S    (OFF_TRS + 128)
#define OFF_U1S    (OFF_H2S + 128)
#define OFF_B1S    (OFF_U1S + 128)
#define OFF_B2S    (OFF_B1S + 128)
#define OFF_XCUR   (OFF_B2S + 128)
#define OFF_B3S    (OFF_XCUR + 32)
#define OFF_PRECS  (OFF_B3S + 32)
#define OFF_KS     (OFF_PRECS + 32)
#define OFF_RED    (OFF_KS + 6 * 34)
#define OFF_SCAL   (OFF_RED + 4)
#define SMEM_FLOATS (OFF_SCAL + 4)
#define SMEM_BYTES (SMEM_FLOATS * sizeof(float))

__global__ __launch_bounds__(NTHREADS, 1) void ode_kernel(
    const float* __restrict__ x0g, const float* __restrict__ W1g,
    const float* __restrict__ u1g, const float* __restrict__ b1g,
    const float* __restrict__ W2g, const float* __restrict__ b2g,
    const float* __restrict__ W3g, const float* __restrict__ b3g,
    const float* __restrict__ precg, float* __restrict__ out) {
    extern __shared__ float sm[];
    float* z1part = sm + OFF_Z1PART;
    float2* part2 = (float2*)(sm + OFF_PART2);
    float* part = sm + OFF_PART;
    float2* hd2 = (float2*)(sm + OFF_HD2);
    float* trs = sm + OFF_TRS;
    float* h2s = sm + OFF_H2S;
    float* u1s = sm + OFF_U1S;
    float* b1s = sm + OFF_B1S;
    float* b2s = sm + OFF_B2S;
    float* xcur = sm + OFF_XCUR;
    float* b3s = sm + OFF_B3S;
    float* precs = sm + OFF_PRECS;
    float* ks = sm + OFF_KS;
    float* red = sm + OFF_RED;
    float* scal = sm + OFF_SCAL;

    const int tid = threadIdx.x;
    const int b = blockIdx.x;
    const int p = tid & 127;     // output index within H
    const int c = tid >> 7;      // chunk 0..3 over q/k reduction dim
    const int i3 = tid & 31;     // W3 output index
    const int g3 = tid >> 5;     // W3 chunk 0..15

    // ---- register-cached weights (loaded once) ----
    // W2A[j] packs {W2[p][q], A[q][p]} for q = c*32+j (for fma.rn.f32x2)
    unsigned long long W2A[32];
    float W1r[8], W3r[8];
#pragma unroll
    for (int j = 0; j < 32; ++j) {
        int q = c * 32 + j;
        float w2v = W2g[p * H + q];
        float av = g_A[q * H + p];
        asm("mov.b64 %0, {%1, %2};" : "=l"(W2A[j]) : "f"(w2v), "f"(av));
    }
#pragma unroll
    for (int j = 0; j < 8; ++j)
        W1r[j] = W1g[p * D + c * 8 + j];   // W1[p][k]
#pragma unroll
    for (int j = 0; j < 8; ++j)
        W3r[j] = W3g[i3 * H + g3 * 8 + j]; // W3[i][p]

    // ---- small params into shared ----
    if (tid < H) {
        u1s[tid] = u1g[tid];
        b1s[tid] = b1g[tid];
        b2s[tid] = b2g[tid];
    }
    if (tid < D) {
        b3s[tid] = b3g[tid];
        precs[tid] = precg[tid];
        xcur[tid] = x0g[b * D + tid];
    }
    if (tid == 0) { scal[0] = 0.f; scal[1] = 0.f; }
    __syncthreads();

    for (int s = 0; s < NSTEPS; ++s) {
        const float t0 = (float)s * DT;
        for (int st = 0; st < 6; ++st) {
            const float t = fmaf(c_c[st], DT, t0);

            // ---- z1 partials with inline stage-x recompute ----
            {
                float acc = 0.f;
#pragma unroll
                for (int j = 0; j < 8; ++j) {
                    int k = c * 8 + j;
                    float xv = xcur[k];
                    for (int jj = 0; jj < st; ++jj)
                        xv = fmaf(DT * c_a[st][jj], ks[jj * 34 + k], xv);
                    acc = fmaf(W1r[j], xv, acc);
                }
                z1part[c * 128 + p] = acc;
            }
            __syncthreads();

            // ---- h1 finalize (first 128 threads) ----
            if (tid < H) {
                float z1 = z1part[tid] + z1part[128 + tid] + z1part[256 + tid] +
                           z1part[384 + tid];
                z1 = fmaf(t, u1s[tid], z1 + b1s[tid]);
                float h1 = tanh_fast(z1);
                hd2[tid] = make_float2(h1, 1.f - h1 * h1);
            }
            __syncthreads();

            // ---- hot loop: paired z2/av via fma.rn.f32x2 ----
            {
                unsigned long long acc0 = 0ull, acc1 = 0ull, acc2 = 0ull, acc3 = 0ull;
                const unsigned long long* hdq =
                    reinterpret_cast<const unsigned long long*>(hd2) + c * 32;
#pragma unroll
                for (int j = 0; j < 32; j += 4) {
                    asm("fma.rn.f32x2 %0, %1, %2, %0;" : "+l"(acc0) : "l"(W2A[j + 0]), "l"(hdq[j + 0]));
                    asm("fma.rn.f32x2 %0, %1, %2, %0;" : "+l"(acc1) : "l"(W2A[j + 1]), "l"(hdq[j + 1]));
                    asm("fma.rn.f32x2 %0, %1, %2, %0;" : "+l"(acc2) : "l"(W2A[j + 2]), "l"(hdq[j + 2]));
                    asm("fma.rn.f32x2 %0, %1, %2, %0;" : "+l"(acc3) : "l"(W2A[j + 3]), "l"(hdq[j + 3]));
                }
                asm("add.rn.f32x2 %0, %0, %1;" : "+l"(acc0) : "l"(acc1));
                asm("add.rn.f32x2 %0, %0, %1;" : "+l"(acc2) : "l"(acc3));
                asm("add.rn.f32x2 %0, %0, %1;" : "+l"(acc0) : "l"(acc2));
                float z2p, avp;
                asm("mov.b64 {%0, %1}, %2;" : "=f"(z2p), "=f"(avp) : "l"(acc0));
                part2[c * 128 + p] = make_float2(z2p, avp);
            }
            __syncthreads();

            // ---- h2 finalize (first 128 threads) ----
            if (tid < H) {
                float2 a0 = part2[tid];
                float2 a1 = part2[128 + tid];
                float2 a2 = part2[256 + tid];
                float2 a3 = part2[384 + tid];
                float z2 = a0.x + a1.x + a2.x + a3.x + b2s[tid];
                float av = a0.y + a1.y + a2.y + a3.y;
                float h2 = tanh_fast(z2);
                h2s[tid] = h2;
                trs[tid] = (1.f - h2 * h2) * av;
            }
            __syncthreads();

            // ---- W3 partials (all threads); trace reduce (warp 1, in addition) ----
            {
                float o = 0.f;
#pragma unroll
                for (int j = 0; j < 8; ++j)
                    o = fmaf(W3r[j], h2s[g3 * 8 + j], o);
                part[g3 * 32 + i3] = o;
            }
            if ((tid >> 5) == 1) {
                int l = tid & 31;
                float tsum = trs[l] + trs[l + 32] + trs[l + 64] + trs[l + 96];
#pragma unroll
                for (int off = 16; off; off >>= 1)
                    tsum += __shfl_down_sync(0xffffffffu, tsum, off);
                if (l == 0) red[2] = tsum;
            }
            __syncthreads();

            // ---- finalize k_st (warp 0) ----
            if (tid < D) {
                float dx = b3s[tid];
#pragma unroll
                for (int g = 0; g < 16; ++g)
                    dx += part[g * 32 + tid];
                ks[st * 34 + tid] = dx;
                // recompute stage x for this lane
                float xv = xcur[tid];
                for (int jj = 0; jj < st; ++jj)
                    xv = fmaf(DT * c_a[st][jj], ks[jj * 34 + tid], xv);
                float lp = fmaf(-0.5f * xv, xv, -0.5f * LOG2PI);
                float s1 = lp * dx;
                float s2 = -precs[tid] * xv * dx;
#pragma unroll
                for (int off = 16; off; off >>= 1) {
                    s1 += __shfl_down_sync(0xffffffffu, s1, off);
                    s2 += __shfl_down_sync(0xffffffffu, s2, off);
                }
                if (tid == 0) {
                    float trace = red[2];
                    float dlogp = -trace;
                    float omt = 1.f - t;
                    float dkl = fmaf(-0.5f * omt * omt, s1,
                                fmaf(-0.5f * omt * (1.f + t), s2, omt * dlogp));
                    ks[st * 34 + 32] = dlogp;
                    ks[st * 34 + 33] = dkl;
                }
            }
            __syncthreads();
        }
        // ---- y update ----
        if (tid < D) {
            float xv = xcur[tid];
#pragma unroll
            for (int j = 0; j < 6; ++j)
                xv = fmaf(DT * c_b[j], ks[j * 34 + tid], xv);
            xcur[tid] = xv;
        } else if (tid == 32) {
            float a = scal[0];
#pragma unroll
            for (int j = 0; j < 6; ++j)
                a = fmaf(DT * c_b[j], ks[j * 34 + 32], a);
            scal[0] = a;
        } else if (tid == 33) {
            float a = scal[1];
#pragma unroll
            for (int j = 0; j < 6; ++j)
                a = fmaf(DT * c_b[j], ks[j * 34 + 33], a);
            scal[1] = a;
        }
        __syncthreads();
    }

    // ---- outputs: z [B*D], logp [B], kl [B] ----
    if (tid < D) {
        out[b * D + tid] = xcur[tid];
        float x0v = x0g[b * D + tid];
        float lp = fmaf(-0.5f * x0v, x0v, -0.5f * LOG2PI);
#pragma unroll
        for (int off = 16; off; off >>= 1)
            lp += __shfl_down_sync(0xffffffffu, lp, off);
        if (tid == 0) {
            out[B * D + b] = lp + scal[0];
            out[B * D + B + b] = scal[1];
        }
    }
}

extern "C" void kernel_launch(void* const* d_in, const int* in_sizes, int n_in,
                              void* d_out, int out_size) {
    const float* x0 = (const float*)d_in[0];
    const float* W1 = (const float*)d_in[1];
    const float* u1 = (const float*)d_in[2];
    const float* b1 = (const float*)d_in[3];
    const float* W2 = (const float*)d_in[4];
    const float* b2 = (const float*)d_in[5];
    const float* W3 = (const float*)d_in[6];
    const float* b3 = (const float*)d_in[7];
    const float* prec = (const float*)d_in[8];
    float* out = (float*)d_out;

    prep_A_kernel<<<H, H>>>(W1, W2, W3);
    ode_kernel<<<B, NTHREADS, SMEM_BYTES>>>(x0, W1, u1, b1, W2, b2, W3, b3, prec, out);
}

// round 5
// speedup vs baseline: 1.5503x; 1.5503x over previous
#include <cuda_runtime.h>
#include <math.h>

#define D 32
#define H 128
#define B 128
#define NSTEPS 8
#define NTHREADS 512
#define LOG2PI 1.8378770664093453f
#define DT 0.125f

// A[q][p] = W2[p][q] * M[q][p],  M = W1 @ W3  (trace(J) = d2^T (A d1))
__device__ float g_A[H * H];

__global__ void prep_A_kernel(const float* __restrict__ W1,
                              const float* __restrict__ W2,
                              const float* __restrict__ W3) {
    int q = blockIdx.x;
    int p = threadIdx.x;
    float m = 0.f;
#pragma unroll
    for (int i = 0; i < D; ++i)
        m = fmaf(W1[q * D + i], W3[i * H + p], m);
    g_A[q * H + p] = W2[p * H + q] * m;
}

__constant__ float c_c[6] = {0.f, 0.2f, 0.3f, 0.8f, 8.f / 9.f, 1.f};
__constant__ float c_a[6][5] = {
    {0.f, 0.f, 0.f, 0.f, 0.f},
    {0.2f, 0.f, 0.f, 0.f, 0.f},
    {3.f / 40.f, 9.f / 40.f, 0.f, 0.f, 0.f},
    {44.f / 45.f, -56.f / 15.f, 32.f / 9.f, 0.f, 0.f},
    {19372.f / 6561.f, -25360.f / 2187.f, 64448.f / 6561.f, -212.f / 729.f, 0.f},
    {9017.f / 3168.f, -355.f / 33.f, 46732.f / 5247.f, 49.f / 176.f, -5103.f / 18656.f}};
__constant__ float c_b[6] = {35.f / 384.f, 0.f, 500.f / 1113.f, 125.f / 192.f,
                             -2187.f / 6784.f, 11.f / 84.f};

__device__ __forceinline__ float tanh_fast(float x) {
    float r;
    asm("tanh.approx.f32 %0, %1;" : "=f"(r) : "f"(x));
    return r;
}

// shared memory layout (floats)
#define OFF_Z1PART 0
#define OFF_PART2  (OFF_Z1PART + 512)
#define OFF_PART   (OFF_PART2 + 1024)
#define OFF_HD2    (OFF_PART + 512)
#define OFF_TRS    (OFF_HD2 + 256)
#define OFF_H2S    (OFF_TRS + 128)
#define OFF_U1S    (OFF_H2S + 128)
#define OFF_B1S    (OFF_U1S + 128)
#define OFF_B2S    (OFF_B1S + 128)
#define OFF_XS     (OFF_B2S + 128)
#define OFF_XCUR   (OFF_XS + 32)
#define OFF_B3S    (OFF_XCUR + 32)
#define OFF_PRECS  (OFF_B3S + 32)
#define OFF_KS     (OFF_PRECS + 32)
#define OFF_RED    (OFF_KS + 6 * 34)
#define OFF_SCAL   (OFF_RED + 4)
#define SMEM_FLOATS (OFF_SCAL + 4)
#define SMEM_BYTES (SMEM_FLOATS * sizeof(float))

__global__ __launch_bounds__(NTHREADS, 1) void ode_kernel(
    const float* __restrict__ x0g, const float* __restrict__ W1g,
    const float* __restrict__ u1g, const float* __restrict__ b1g,
    const float* __restrict__ W2g, const float* __restrict__ b2g,
    const float* __restrict__ W3g, const float* __restrict__ b3g,
    const float* __restrict__ precg, float* __restrict__ out) {
    extern __shared__ float sm[];
    float* z1part = sm + OFF_Z1PART;
    float2* part2 = (float2*)(sm + OFF_PART2);
    float* part = sm + OFF_PART;
    float2* hd2 = (float2*)(sm + OFF_HD2);
    float* trs = sm + OFF_TRS;
    float* h2s = sm + OFF_H2S;
    float* u1s = sm + OFF_U1S;
    float* b1s = sm + OFF_B1S;
    float* b2s = sm + OFF_B2S;
    float* xs = sm + OFF_XS;
    float* xcur = sm + OFF_XCUR;
    float* b3s = sm + OFF_B3S;
    float* precs = sm + OFF_PRECS;
    float* ks = sm + OFF_KS;
    float* red = sm + OFF_RED;
    float* scal = sm + OFF_SCAL;

    const int tid = threadIdx.x;
    const int b = blockIdx.x;
    const int p = tid & 127;     // output index within H
    const int c = tid >> 7;      // chunk 0..3 over q/k reduction dim
    const int i3 = tid & 31;     // W3 output index
    const int g3 = tid >> 5;     // W3 chunk 0..15

    // ---- register-cached weights (loaded once), scalar floats (no pairing) ----
    float W2r[32], Ar[32], W1r[8], W3r[8];
#pragma unroll
    for (int j = 0; j < 32; ++j) {
        int q = c * 32 + j;
        W2r[j] = W2g[p * H + q];   // W2[p][q]
        Ar[j] = g_A[q * H + p];    // A[q][p]
    }
#pragma unroll
    for (int j = 0; j < 8; ++j)
        W1r[j] = W1g[p * D + c * 8 + j];   // W1[p][k]
#pragma unroll
    for (int j = 0; j < 8; ++j)
        W3r[j] = W3g[i3 * H + g3 * 8 + j]; // W3[i][p]

    // ---- small params into shared ----
    if (tid < H) {
        u1s[tid] = u1g[tid];
        b1s[tid] = b1g[tid];
        b2s[tid] = b2g[tid];
    }
    if (tid < D) {
        b3s[tid] = b3g[tid];
        precs[tid] = precg[tid];
        xcur[tid] = x0g[b * D + tid];
    }
    if (tid == 0) { scal[0] = 0.f; scal[1] = 0.f; }
    __syncthreads();

    for (int s = 0; s < NSTEPS; ++s) {
        const float t0 = (float)s * DT;
        for (int st = 0; st < 6; ++st) {
            // ---- stage input x ----
            if (tid < D) {
                float xv = xcur[tid];
                for (int j = 0; j < st; ++j)
                    xv = fmaf(DT * c_a[st][j], ks[j * 34 + tid], xv);
                xs[tid] = xv;
            }
            __syncthreads();
            const float t = fmaf(c_c[st], DT, t0);

            // ---- z1 partials: thread (c,p), k-range 8 ----
            {
                float acc = 0.f;
#pragma unroll
                for (int j = 0; j < 8; ++j)
                    acc = fmaf(W1r[j], xs[c * 8 + j], acc);
                z1part[c * 128 + p] = acc;
            }
            __syncthreads();

            // ---- h1 finalize (first 128 threads) ----
            if (tid < H) {
                float z1 = z1part[tid] + z1part[128 + tid] + z1part[256 + tid] +
                           z1part[384 + tid];
                z1 = fmaf(t, u1s[tid], z1 + b1s[tid]);
                float h1 = tanh_fast(z1);
                hd2[tid] = make_float2(h1, 1.f - h1 * h1);
            }
            __syncthreads();

            // ---- hot loop: z2/av partials, float4 broadcast loads (2 hd pairs) ----
            {
                float z2a = 0.f, z2b = 0.f, ava = 0.f, avb = 0.f;
                const float4* hd4 = reinterpret_cast<const float4*>(hd2) + c * 16;
#pragma unroll
                for (int j = 0; j < 16; ++j) {
                    float4 hh = hd4[j];   // {h1[2j], d1[2j], h1[2j+1], d1[2j+1]}
                    z2a = fmaf(W2r[2 * j], hh.x, z2a);
                    ava = fmaf(Ar[2 * j], hh.y, ava);
                    z2b = fmaf(W2r[2 * j + 1], hh.z, z2b);
                    avb = fmaf(Ar[2 * j + 1], hh.w, avb);
                }
                part2[c * 128 + p] = make_float2(z2a + z2b, ava + avb);
            }
            __syncthreads();

            // ---- h2 finalize (first 128 threads) ----
            if (tid < H) {
                float2 a0 = part2[tid];
                float2 a1 = part2[128 + tid];
                float2 a2 = part2[256 + tid];
                float2 a3 = part2[384 + tid];
                float z2 = a0.x + a1.x + a2.x + a3.x + b2s[tid];
                float av = a0.y + a1.y + a2.y + a3.y;
                float h2 = tanh_fast(z2);
                h2s[tid] = h2;
                trs[tid] = (1.f - h2 * h2) * av;
            }
            __syncthreads();

            // ---- W3 partials (all threads); trace reduce (warp 1) ----
            {
                float o = 0.f;
#pragma unroll
                for (int j = 0; j < 8; ++j)
                    o = fmaf(W3r[j], h2s[g3 * 8 + j], o);
                part[g3 * 32 + i3] = o;
            }
            if ((tid >> 5) == 1) {
                int l = tid & 31;
                float tsum = trs[l] + trs[l + 32] + trs[l + 64] + trs[l + 96];
#pragma unroll
                for (int off = 16; off; off >>= 1)
                    tsum += __shfl_down_sync(0xffffffffu, tsum, off);
                if (l == 0) red[2] = tsum;
            }
            __syncthreads();

            // ---- finalize k_st (warp 0) ----
            if (tid < D) {
                float dx = b3s[tid];
#pragma unroll
                for (int g = 0; g < 16; ++g)
                    dx += part[g * 32 + tid];
                ks[st * 34 + tid] = dx;
                float xv = xs[tid];
                float lp = fmaf(-0.5f * xv, xv, -0.5f * LOG2PI);
                float s1 = lp * dx;
                float s2 = -precs[tid] * xv * dx;
#pragma unroll
                for (int off = 16; off; off >>= 1) {
                    s1 += __shfl_down_sync(0xffffffffu, s1, off);
                    s2 += __shfl_down_sync(0xffffffffu, s2, off);
                }
                if (tid == 0) {
                    float trace = red[2];
                    float dlogp = -trace;
                    float omt = 1.f - t;
                    float dkl = fmaf(-0.5f * omt * omt, s1,
                                fmaf(-0.5f * omt * (1.f + t), s2, omt * dlogp));
                    ks[st * 34 + 32] = dlogp;
                    ks[st * 34 + 33] = dkl;
                }
            }
            __syncthreads();
        }
        // ---- y update ----
        if (tid < D) {
            float xv = xcur[tid];
#pragma unroll
            for (int j = 0; j < 6; ++j)
                xv = fmaf(DT * c_b[j], ks[j * 34 + tid], xv);
            xcur[tid] = xv;
        } else if (tid == 32) {
            float a = scal[0];
#pragma unroll
            for (int j = 0; j < 6; ++j)
                a = fmaf(DT * c_b[j], ks[j * 34 + 32], a);
            scal[0] = a;
        } else if (tid == 33) {
            float a = scal[1];
#pragma unroll
            for (int j = 0; j < 6; ++j)
                a = fmaf(DT * c_b[j], ks[j * 34 + 33], a);
            scal[1] = a;
        }
        __syncthreads();
    }

    // ---- outputs: z [B*D], logp [B], kl [B] ----
    if (tid < D) {
        out[b * D + tid] = xcur[tid];
        float x0v = x0g[b * D + tid];
        float lp = fmaf(-0.5f * x0v, x0v, -0.5f * LOG2PI);
#pragma unroll
        for (int off = 16; off; off >>= 1)
            lp += __shfl_down_sync(0xffffffffu, lp, off);
        if (tid == 0) {
            out[B * D + b] = lp + scal[0];
            out[B * D + B + b] = scal[1];
        }
    }
}

extern "C" void kernel_launch(void* const* d_in, const int* in_sizes, int n_in,
                              void* d_out, int out_size) {
    const float* x0 = (const float*)d_in[0];
    const float* W1 = (const float*)d_in[1];
    const float* u1 = (const float*)d_in[2];
    const float* b1 = (const float*)d_in[3];
    const float* W2 = (const float*)d_in[4];
    const float* b2 = (const float*)d_in[5];
    const float* W3 = (const float*)d_in[6];
    const float* b3 = (const float*)d_in[7];
    const float* prec = (const float*)d_in[8];
    float* out = (float*)d_out;

    prep_A_kernel<<<H, H>>>(W1, W2, W3);
    ode_kernel<<<B, NTHREADS, SMEM_BYTES>>>(x0, W1, u1, b1, W2, b2, W3, b3, prec, out);
}